// round 4
// baseline (speedup 1.0000x reference)
#include <cuda_runtime.h>
#include <cuda_bf16.h>
#include <cuda_fp16.h>
#include <mma.h>
#include <cstdint>

using namespace nvcuda;

#define BATCH 16
#define L 1024
#define D 768
#define G2 768            // group rows per batch (max g = 511+255 = 766)
#define BIG 1e30f

// -------- device scratch (allocation-free rule: __device__ globals) --------
__device__ __nv_bfloat16 g_s1n[BATCH * L * D];                 // 25 MB
__device__ __nv_bfloat16 g_s2n[BATCH * L * D];                 // 25 MB
// dist (=1-dot) as half, DTW-step layout: cell (i,j) ->
// g_dskH[b][g][jg][r][c], g = i/2 + j/4, jg = j/4, r = i&1, c = j&3.
// One g row = 256 jgroups * 8 halfs = 4 KB.
__device__ __half g_dskH[(size_t)BATCH * G2 * 2048];           // 48 MB

// ---------------------------------------------------------------------------
// helpers
// ---------------------------------------------------------------------------
__device__ __forceinline__ uint32_t smem_u32(const void* p) {
    uint32_t a;
    asm("{ .reg .u64 t; cvta.to.shared.u64 t, %1; cvt.u32.u64 %0, t; }"
        : "=r"(a) : "l"(p));
    return a;
}
__device__ __forceinline__ void cp16(uint32_t dst, const void* src) {
    asm volatile("cp.async.cg.shared.global [%0], [%1], 16;"
                 :: "r"(dst), "l"(src) : "memory");
}
#define CP_COMMIT() asm volatile("cp.async.commit_group;" ::: "memory")
#define CP_WAIT1()  asm volatile("cp.async.wait_group 1;" ::: "memory")

// ---------------------------------------------------------------------------
// Kernel 1: L2-normalize. One warp per row, float4 loads, shfl reduction.
// ---------------------------------------------------------------------------
__global__ __launch_bounds__(256) void normalize_kernel(const float* __restrict__ s1,
                                                        const float* __restrict__ s2) {
    int wid = threadIdx.x >> 5, lane = threadIdx.x & 31;
    int row = blockIdx.x * 8 + wid;          // 0 .. 32767
    const float* src;
    __nv_bfloat16* dst;
    if (row < BATCH * L) {
        src = s1 + (size_t)row * D;
        dst = g_s1n + (size_t)row * D;
    } else {
        int r = row - BATCH * L;
        src = s2 + (size_t)r * D;
        dst = g_s2n + (size_t)r * D;
    }
    const float4* s4 = (const float4*)src;
    float4 v[6];
    float ss = 0.f;
    #pragma unroll
    for (int i = 0; i < 6; i++) {
        v[i] = s4[lane + 32 * i];
        ss += v[i].x * v[i].x + v[i].y * v[i].y + v[i].z * v[i].z + v[i].w * v[i].w;
    }
    #pragma unroll
    for (int o = 16; o > 0; o >>= 1) ss += __shfl_xor_sync(0xffffffffu, ss, o);
    float inv = rsqrtf(ss);
    #pragma unroll
    for (int i = 0; i < 6; i++) {
        __nv_bfloat162 a = __floats2bfloat162_rn(v[i].x * inv, v[i].y * inv);
        __nv_bfloat162 b = __floats2bfloat162_rn(v[i].z * inv, v[i].w * inv);
        uint2 pk;
        pk.x = *(const uint32_t*)&a;
        pk.y = *(const uint32_t*)&b;
        ((uint2*)dst)[lane + 32 * i] = pk;
    }
}

// ---------------------------------------------------------------------------
// Kernel 2: wmma bf16 GEMM, cp.async 3-stage pipeline. CTA 256x128, BK=32,
// 8 warps, warp tile 64x64 (acc 4x4). Epilogue: acc -> smem (two m-halves) ->
// packed half uint4 stores into g_dskH.
// ---------------------------------------------------------------------------
#define BM 256
#define BN 128
#define BK 32
#define STAGES 3
#define NITER (D / BK)    // 24
#define LDA_S 48          // padded bf16 smem row
#define LDC_S 132         // padded fp32 epi row (128 cols + 4)
#define STA_ELEMS (BM * LDA_S)                // A per stage (bf16)
#define STB_ELEMS (BN * LDA_S)                // B per stage
#define STAGE_BYTES ((STA_ELEMS + STB_ELEMS) * 2)   // 36864 B
#define SMEM_BYTES (STAGES * STAGE_BYTES)           // 110592 B

__global__ __launch_bounds__(256) void gemm_dist_kernel() {
    extern __shared__ char smem[];
    __nv_bfloat16* sA[STAGES];
    __nv_bfloat16* sB[STAGES];
    #pragma unroll
    for (int s = 0; s < STAGES; s++) {
        sA[s] = (__nv_bfloat16*)(smem + s * STAGE_BYTES);
        sB[s] = sA[s] + STA_ELEMS;
    }

    int tid = threadIdx.x;
    int b  = blockIdx.z;
    int m0 = blockIdx.y * BM;
    int n0 = blockIdx.x * BN;
    const __nv_bfloat16* A  = g_s1n + (size_t)b * L * D;
    const __nv_bfloat16* Bm = g_s2n + (size_t)b * L * D;

    int warp = tid >> 5;
    int wm = warp & 3;        // 4 warps in M (64 rows each)
    int wn = warp >> 2;       // 2 warps in N (64 cols each)

    // load indices: chunk id = tid + it*256, row = id>>2, col = (id&3)*8
    int lr = tid >> 2;
    int lc = (tid & 3) * 8;

    wmma::fragment<wmma::accumulator, 16, 16, 16, float> acc[4][4];
    #pragma unroll
    for (int mi = 0; mi < 4; mi++)
        #pragma unroll
        for (int ni = 0; ni < 4; ni++)
            wmma::fill_fragment(acc[mi][ni], 0.0f);

    // prologue: stage 0, 1
    #pragma unroll
    for (int s = 0; s < 2; s++) {
        int k0 = s * BK;
        #pragma unroll
        for (int it = 0; it < 4; it++)    // A: 1024 chunks
            cp16(smem_u32(&sA[s][(lr + it * 64) * LDA_S + lc]),
                 A + (size_t)(m0 + lr + it * 64) * D + k0 + lc);
        #pragma unroll
        for (int it = 0; it < 2; it++)    // B: 512 chunks
            cp16(smem_u32(&sB[s][(lr + it * 64) * LDA_S + lc]),
                 Bm + (size_t)(n0 + lr + it * 64) * D + k0 + lc);
        CP_COMMIT();
    }

    for (int c = 0; c < NITER; c++) {
        CP_WAIT1();
        __syncthreads();
        int st = c % STAGES;

        #pragma unroll
        for (int kk = 0; kk < BK; kk += 16) {
            wmma::fragment<wmma::matrix_a, 16, 16, 16, __nv_bfloat16, wmma::row_major> af[4];
            wmma::fragment<wmma::matrix_b, 16, 16, 16, __nv_bfloat16, wmma::col_major> bf[4];
            #pragma unroll
            for (int mi = 0; mi < 4; mi++)
                wmma::load_matrix_sync(af[mi], &sA[st][(wm * 64 + mi * 16) * LDA_S + kk], LDA_S);
            #pragma unroll
            for (int ni = 0; ni < 4; ni++)
                wmma::load_matrix_sync(bf[ni], &sB[st][(wn * 64 + ni * 16) * LDA_S + kk], LDA_S);
            #pragma unroll
            for (int mi = 0; mi < 4; mi++)
                #pragma unroll
                for (int ni = 0; ni < 4; ni++)
                    wmma::mma_sync(acc[mi][ni], af[mi], bf[ni], acc[mi][ni]);
        }

        if (c + 2 < NITER) {
            int sn = (c + 2) % STAGES;
            int k0 = (c + 2) * BK;
            #pragma unroll
            for (int it = 0; it < 4; it++)
                cp16(smem_u32(&sA[sn][(lr + it * 64) * LDA_S + lc]),
                     A + (size_t)(m0 + lr + it * 64) * D + k0 + lc);
            #pragma unroll
            for (int it = 0; it < 2; it++)
                cp16(smem_u32(&sB[sn][(lr + it * 64) * LDA_S + lc]),
                     Bm + (size_t)(n0 + lr + it * 64) * D + k0 + lc);
        }
        CP_COMMIT();
    }

    // epilogue: two m-halves of 128 rows through smem, packed half stores
    float* Cs = (float*)smem;
    __half* dbase = g_dskH + (size_t)b * G2 * 2048;
    int jgl = tid & 31;           // local j group (4 cols)
    int sub = tid >> 5;           // 0..7

    #pragma unroll
    for (int mh = 0; mh < 2; mh++) {
        __syncthreads();
        if ((wm >> 1) == mh) {
            #pragma unroll
            for (int mi = 0; mi < 4; mi++)
                #pragma unroll
                for (int ni = 0; ni < 4; ni++)
                    wmma::store_matrix_sync(
                        &Cs[((wm & 1) * 64 + mi * 16) * LDC_S + (wn * 64 + ni * 16)],
                        acc[mi][ni], LDC_S, wmma::mem_row_major);
        }
        __syncthreads();

        #pragma unroll
        for (int it = 0; it < 8; it++) {
            int il2 = sub + it * 8;                      // local row pair 0..63
            float4 r0 = *(float4*)&Cs[(2 * il2)     * LDC_S + 4 * jgl];
            float4 r1 = *(float4*)&Cs[(2 * il2 + 1) * LDC_S + 4 * jgl];
            uint4 o;
            __half2* ph = (__half2*)&o;
            ph[0] = __floats2half2_rn(1.0f - r0.x, 1.0f - r0.y);
            ph[1] = __floats2half2_rn(1.0f - r0.z, 1.0f - r0.w);
            ph[2] = __floats2half2_rn(1.0f - r1.x, 1.0f - r1.y);
            ph[3] = __floats2half2_rn(1.0f - r1.z, 1.0f - r1.w);
            int g = (m0 >> 1) + mh * 64 + il2 + (n0 >> 2) + jgl;
            *(uint4*)(dbase + (size_t)g * 2048 + ((n0 >> 2) + jgl) * 8) = o;
        }
    }
}

// ---------------------------------------------------------------------------
// Kernel 3: DTW wavefront. 256 threads, thread jg owns cols [4jg,4jg+4),
// 2 rows per macro-step, 767 active steps (run 768). One uint4 (8 half)
// dist load per thread per step. Min-plus prefix form: per-cell critical
// chain is a single fmin. Neighbor handoff via shfl + parity smem.
// ---------------------------------------------------------------------------
#define PF 8

__global__ __launch_bounds__(256) void dtw_kernel(float* __restrict__ out) {
    int b = blockIdx.x;
    int jg = threadIdx.x, lane = jg & 31, w = jg >> 5;

    const uint4* base = (const uint4*)(g_dskH + (size_t)b * G2 * 2048) + jg;
    // g row stride = 2048 halfs = 256 uint4

    __shared__ float pub[2][8][2];
    if (lane < 2) { pub[0][w][lane] = BIG; pub[1][w][lane] = BIG; }
    __syncthreads();

    float p0 = BIG, p1 = BIG, p2 = BIG, p3 = BIG;   // prev row of own 4 cols
    float c3r0 = BIG, c3r1 = BIG, prev_vb = BIG;
    float res = 0.0f;

    uint4 ring[PF];
    #pragma unroll
    for (int s = 0; s < PF; s++)
        ring[s] = base[(size_t)min(s, G2 - 1) * 256];

    #pragma unroll 8
    for (int S = 0; S < 768; S++) {
        uint4 u = ring[S & (PF - 1)];
        ring[S & (PF - 1)] = base[(size_t)min(S + PF, G2 - 1) * 256];

        float va = __shfl_up_sync(0xffffffffu, c3r0, 1);  // dtw[i0][4jg-1]
        float vb = __shfl_up_sync(0xffffffffu, c3r1, 1);  // dtw[i0+1][4jg-1]
        if (lane == 0) {
            if (w > 0) {
                va = pub[(S & 1) ^ 1][w - 1][0];
                vb = pub[(S & 1) ^ 1][w - 1][1];
            } else { va = BIG; vb = BIG; }
        }

        int i0 = 2 * (S - jg);
        if ((unsigned)i0 < 1024u) {
            float2 q0 = __half22float2(((const __half2*)&u)[0]);
            float2 q1 = __half22float2(((const __half2*)&u)[1]);
            float2 q2 = __half22float2(((const __half2*)&u)[2]);
            float2 q3 = __half22float2(((const __half2*)&u)[3]);
            // row i0 (min-plus prefix form)
            float D0 = q0.x, D1 = D0 + q0.y, D2 = D1 + q1.x, D3 = D2 + q1.y;
            float f0 = fminf(prev_vb, p0);
            float f1 = fminf(p0, p1) - D0;
            float f2 = fminf(p1, p2) - D1;
            float f3 = fminf(p2, p3) - D2;
            float m0 = fminf(va, f0);
            if (i0 == 0 && jg == 0) m0 = 0.0f;
            float m1 = fminf(m0, f1);
            float m2 = fminf(m1, f2);
            float m3 = fminf(m2, f3);
            float c0 = D0 + m0, c1 = D1 + m1, c2 = D2 + m2, c3 = D3 + m3;
            // row i0+1
            float E0 = q2.x, E1 = E0 + q2.y, E2 = E1 + q3.x, E3 = E2 + q3.y;
            float h0 = fminf(va, c0);
            float h1 = fminf(c0, c1) - E0;
            float h2 = fminf(c1, c2) - E1;
            float h3 = fminf(c2, c3) - E2;
            float n0 = fminf(vb, h0);
            float n1 = fminf(n0, h1);
            float n2 = fminf(n1, h2);
            float n3 = fminf(n2, h3);
            p0 = E0 + n0; p1 = E1 + n1; p2 = E2 + n2; p3 = E3 + n3;
            c3r0 = c3; c3r1 = p3;
            if (i0 == 1022 && jg == 255) res = p3;
        }
        prev_vb = vb;
        if (lane == 31) { pub[S & 1][w][0] = c3r0; pub[S & 1][w][1] = c3r1; }
        __syncthreads();
    }

    if (jg == 255)
        out[b] = 1.0f / (1.0f + res * (1.0f / 2048.0f));
}

// ---------------------------------------------------------------------------
extern "C" void kernel_launch(void* const* d_in, const int* in_sizes, int n_in,
                              void* d_out, int out_size) {
    const float* s1 = (const float*)d_in[0];
    const float* s2 = (const float*)d_in[1];
    float* out = (float*)d_out;

    cudaFuncSetAttribute(gemm_dist_kernel,
                         cudaFuncAttributeMaxDynamicSharedMemorySize, SMEM_BYTES);

    normalize_kernel<<<4096, 256>>>(s1, s2);
    gemm_dist_kernel<<<dim3(L / BN, L / BM, BATCH), 256, SMEM_BYTES>>>();
    dtw_kernel<<<BATCH, 256>>>(out);
}